// round 1
// baseline (speedup 1.0000x reference)
#include <cuda_runtime.h>
#include <math.h>

#define BATCH 2
#define SEQ   2048
#define NH    16
#define DK    64
#define DM    1024
#define MTOT  (BATCH*SEQ)          // 4096

// d_out layout: [out 4194304][std_w 100663296][spec_w 33554432]
#define STD_OFF  4194304ull
#define SPEC_OFF 104857600ull

// scratch (no allocations allowed)
__device__ float g_q[(size_t)BATCH*NH*SEQ*DK];
__device__ float g_k[(size_t)BATCH*NH*SEQ*DK];
__device__ float g_v[(size_t)BATCH*NH*SEQ*DK];
__device__ float g_attn[(size_t)BATCH*SEQ*DM];

__device__ __forceinline__ float* head_w_ptr(float* dout, int bh) {
    int b = bh >> 4, h = bh & 15;
    size_t off;
    if (h < 12) off = STD_OFF  + ((size_t)(b * 12 + h))      * SEQ * SEQ;
    else        off = SPEC_OFF + ((size_t)(b * 4 + (h - 12))) * SEQ * SEQ;
    return dout + off;
}

// ---------------------------------------------------------------------------
// Generic projection GEMM: C = A[M,K=1024] @ W[1024, N=1024] + bias
// which: 0->g_q, 1->g_k, 2->g_v (scatter to [B,H,S,Dk]), 3->Cout row-major
// a_is_attn: read A from g_attn instead of param pointer.
// Tile 128x128x8, 256 threads, 8x8 per thread (4+4 split).
// ---------------------------------------------------------------------------
__global__ __launch_bounds__(256) void proj_kernel(
    const float* __restrict__ A, const float* __restrict__ W,
    const float* __restrict__ bias, float* __restrict__ Cout,
    int which, int a_is_attn)
{
    const int K = DM, N = DM;
    __shared__ float As[8][128];
    __shared__ float Bs[8][128];

    const float* Abase = a_is_attn ? (const float*)g_attn : A;

    int tid = threadIdx.x;
    int bm = blockIdx.y * 128, bn = blockIdx.x * 128;
    int a_row = tid >> 1, a_col = (tid & 1) * 4;
    int b_row = tid >> 5, b_col = (tid & 31) * 4;
    int ty = tid >> 4, tx = tid & 15;

    float acc[8][8];
#pragma unroll
    for (int i = 0; i < 8; i++)
#pragma unroll
        for (int j = 0; j < 8; j++) acc[i][j] = 0.f;

    const float* Ap = Abase + (size_t)(bm + a_row) * K + a_col;
    const float* Wp = W + (size_t)b_row * N + bn + b_col;

    for (int k0 = 0; k0 < K; k0 += 8) {
        float4 av = *(const float4*)(Ap + k0);
        float4 bv = *(const float4*)(Wp + (size_t)k0 * N);
        As[a_col + 0][a_row] = av.x;
        As[a_col + 1][a_row] = av.y;
        As[a_col + 2][a_row] = av.z;
        As[a_col + 3][a_row] = av.w;
        *(float4*)&Bs[b_row][b_col] = bv;
        __syncthreads();
#pragma unroll
        for (int kk = 0; kk < 8; kk++) {
            float a[8], b[8];
            *(float4*)(a)     = *(const float4*)&As[kk][ty * 4];
            *(float4*)(a + 4) = *(const float4*)&As[kk][64 + ty * 4];
            *(float4*)(b)     = *(const float4*)&Bs[kk][tx * 4];
            *(float4*)(b + 4) = *(const float4*)&Bs[kk][64 + tx * 4];
#pragma unroll
            for (int i = 0; i < 8; i++)
#pragma unroll
                for (int j = 0; j < 8; j++)
                    acc[i][j] = fmaf(a[i], b[j], acc[i][j]);
        }
        __syncthreads();
    }

    float* qkv = (which == 0) ? g_q : (which == 1) ? g_k : g_v;
#pragma unroll
    for (int i = 0; i < 8; i++) {
        int m = bm + ((i < 4) ? ty * 4 + i : 64 + ty * 4 + (i - 4));
#pragma unroll
        for (int j = 0; j < 8; j++) {
            int n = bn + ((j < 4) ? tx * 4 + j : 64 + tx * 4 + (j - 4));
            float v = acc[i][j] + bias[n];
            if (which < 3) {
                int b_ = m >> 11, s = m & 2047, h = n >> 6, d = n & 63;
                qkv[((((size_t)b_ * NH) + h) * SEQ + s) * DK + d] = v;
            } else {
                Cout[(size_t)m * N + n] = v;
            }
        }
    }
}

// ---------------------------------------------------------------------------
// Scores: per head, S = q @ k^T * (1/8), written straight into d_out weights.
// Tile 128x128, K=64 (8 iters of BK=8). grid (16,16,32)
// ---------------------------------------------------------------------------
__global__ __launch_bounds__(256) void scores_kernel(float* __restrict__ dout)
{
    int bh = blockIdx.z;
    const float* q = g_q + (size_t)bh * SEQ * DK;
    const float* k = g_k + (size_t)bh * SEQ * DK;
    float* outp = head_w_ptr(dout, bh);

    __shared__ float As[8][128];
    __shared__ float Bs[8][128];

    int tid = threadIdx.x;
    int bm = blockIdx.y * 128, bn = blockIdx.x * 128;
    int r = tid >> 1, c = (tid & 1) * 4;
    int ty = tid >> 4, tx = tid & 15;

    float acc[8][8];
#pragma unroll
    for (int i = 0; i < 8; i++)
#pragma unroll
        for (int j = 0; j < 8; j++) acc[i][j] = 0.f;

    const float* qp = q + (size_t)(bm + r) * DK + c;
    const float* kp = k + (size_t)(bn + r) * DK + c;

    for (int k0 = 0; k0 < DK; k0 += 8) {
        float4 av = *(const float4*)(qp + k0);
        float4 bv = *(const float4*)(kp + k0);
        As[c + 0][r] = av.x; As[c + 1][r] = av.y;
        As[c + 2][r] = av.z; As[c + 3][r] = av.w;
        Bs[c + 0][r] = bv.x; Bs[c + 1][r] = bv.y;
        Bs[c + 2][r] = bv.z; Bs[c + 3][r] = bv.w;
        __syncthreads();
#pragma unroll
        for (int kk = 0; kk < 8; kk++) {
            float a[8], b[8];
            *(float4*)(a)     = *(const float4*)&As[kk][ty * 4];
            *(float4*)(a + 4) = *(const float4*)&As[kk][64 + ty * 4];
            *(float4*)(b)     = *(const float4*)&Bs[kk][tx * 4];
            *(float4*)(b + 4) = *(const float4*)&Bs[kk][64 + tx * 4];
#pragma unroll
            for (int i = 0; i < 8; i++)
#pragma unroll
                for (int j = 0; j < 8; j++)
                    acc[i][j] = fmaf(a[i], b[j], acc[i][j]);
        }
        __syncthreads();
    }

#pragma unroll
    for (int i = 0; i < 8; i++) {
        int m = bm + ((i < 4) ? ty * 4 + i : 64 + ty * 4 + (i - 4));
#pragma unroll
        for (int j = 0; j < 8; j++) {
            int n = bn + ((j < 4) ? tx * 4 + j : 64 + tx * 4 + (j - 4));
            outp[(size_t)m * SEQ + n] = acc[i][j] * 0.125f;
        }
    }
}

// ---------------------------------------------------------------------------
// In-place row softmax over the weights region. 1 block = 1 row of 2048.
// grid = B*H*S = 65536 blocks, 256 threads (8 values / thread).
// ---------------------------------------------------------------------------
__global__ __launch_bounds__(256) void softmax_kernel(float* __restrict__ dout)
{
    int row = blockIdx.x;
    int bh = row >> 11, r = row & 2047;
    float* p = head_w_ptr(dout, bh) + (size_t)r * SEQ;

    int tid = threadIdx.x;
    float4 v0 = *(const float4*)(p + tid * 8);
    float4 v1 = *(const float4*)(p + tid * 8 + 4);
    float vals[8] = {v0.x, v0.y, v0.z, v0.w, v1.x, v1.y, v1.z, v1.w};

    __shared__ float red[8];

    float mx = vals[0];
#pragma unroll
    for (int i = 1; i < 8; i++) mx = fmaxf(mx, vals[i]);
#pragma unroll
    for (int off = 16; off; off >>= 1)
        mx = fmaxf(mx, __shfl_xor_sync(0xffffffffu, mx, off));
    if ((tid & 31) == 0) red[tid >> 5] = mx;
    __syncthreads();
    mx = red[0];
#pragma unroll
    for (int w = 1; w < 8; w++) mx = fmaxf(mx, red[w]);
    __syncthreads();

    float s = 0.f;
#pragma unroll
    for (int i = 0; i < 8; i++) { vals[i] = __expf(vals[i] - mx); s += vals[i]; }
#pragma unroll
    for (int off = 16; off; off >>= 1)
        s += __shfl_xor_sync(0xffffffffu, s, off);
    if ((tid & 31) == 0) red[tid >> 5] = s;
    __syncthreads();
    s = red[0];
#pragma unroll
    for (int w = 1; w < 8; w++) s += red[w];

    float inv = 1.0f / s;
    float4 o0 = make_float4(vals[0] * inv, vals[1] * inv, vals[2] * inv, vals[3] * inv);
    float4 o1 = make_float4(vals[4] * inv, vals[5] * inv, vals[6] * inv, vals[7] * inv);
    *(float4*)(p + tid * 8) = o0;
    *(float4*)(p + tid * 8 + 4) = o1;
}

// ---------------------------------------------------------------------------
// AV: per head, O[S,64] = W[S,S] @ V[S,64]; write to g_attn [B,S,H,Dk].
// Tile 128x64x16, 256 threads, 8x4 per thread. grid (1,16,32)
// ---------------------------------------------------------------------------
__global__ __launch_bounds__(256) void av_kernel(float* __restrict__ dout)
{
    int bh = blockIdx.z;
    int b = bh >> 4, h = bh & 15;
    const float* Wm = head_w_ptr(dout, bh);
    const float* V = g_v + (size_t)bh * SEQ * DK;

    __shared__ float As[16][128];
    __shared__ float Bs[16][64];

    int tid = threadIdx.x;
    int bm = blockIdx.y * 128;
    int a_row = tid & 127, a_c0 = (tid >> 7) * 8;
    int b_row = tid >> 4, b_col = (tid & 15) * 4;
    int ty = tid >> 4, tx = tid & 15;

    float acc[8][4];
#pragma unroll
    for (int i = 0; i < 8; i++)
#pragma unroll
        for (int j = 0; j < 4; j++) acc[i][j] = 0.f;

    const float* Wp = Wm + (size_t)(bm + a_row) * SEQ + a_c0;
    const float* Vp = V + (size_t)b_row * DK + b_col;

    for (int k0 = 0; k0 < SEQ; k0 += 16) {
        float4 a0 = *(const float4*)(Wp + k0);
        float4 a1 = *(const float4*)(Wp + k0 + 4);
        float4 bv = *(const float4*)(Vp + (size_t)k0 * DK);
        As[a_c0 + 0][a_row] = a0.x; As[a_c0 + 1][a_row] = a0.y;
        As[a_c0 + 2][a_row] = a0.z; As[a_c0 + 3][a_row] = a0.w;
        As[a_c0 + 4][a_row] = a1.x; As[a_c0 + 5][a_row] = a1.y;
        As[a_c0 + 6][a_row] = a1.z; As[a_c0 + 7][a_row] = a1.w;
        *(float4*)&Bs[b_row][b_col] = bv;
        __syncthreads();
#pragma unroll
        for (int kk = 0; kk < 16; kk++) {
            float a[8], bb[4];
            *(float4*)(a)     = *(const float4*)&As[kk][ty * 4];
            *(float4*)(a + 4) = *(const float4*)&As[kk][64 + ty * 4];
            *(float4*)(bb)    = *(const float4*)&Bs[kk][tx * 4];
#pragma unroll
            for (int i = 0; i < 8; i++)
#pragma unroll
                for (int j = 0; j < 4; j++)
                    acc[i][j] = fmaf(a[i], bb[j], acc[i][j]);
        }
        __syncthreads();
    }

#pragma unroll
    for (int i = 0; i < 8; i++) {
        int s = bm + ((i < 4) ? ty * 4 + i : 64 + ty * 4 + (i - 4));
#pragma unroll
        for (int j = 0; j < 4; j++) {
            int d = tx * 4 + j;
            g_attn[(((size_t)b * SEQ + s) * NH + h) * DK + d] = acc[i][j];
        }
    }
}

// ---------------------------------------------------------------------------
extern "C" void kernel_launch(void* const* d_in, const int* in_sizes, int n_in,
                              void* d_out, int out_size)
{
    const float* x  = (const float*)d_in[0];
    // d_in[1] = input_ids (unused by reference math)
    const float* Wq = (const float*)d_in[2];
    const float* bq = (const float*)d_in[3];
    const float* Wk = (const float*)d_in[4];
    const float* bk = (const float*)d_in[5];
    const float* Wv = (const float*)d_in[6];
    const float* bv = (const float*)d_in[7];
    const float* Wo = (const float*)d_in[8];
    const float* bo = (const float*)d_in[9];
    float* out = (float*)d_out;

    dim3 blk(256);
    dim3 gproj(DM / 128, MTOT / 128);      // 8 x 32

    proj_kernel<<<gproj, blk>>>(x, Wq, bq, nullptr, 0, 0);
    proj_kernel<<<gproj, blk>>>(x, Wk, bk, nullptr, 1, 0);
    proj_kernel<<<gproj, blk>>>(x, Wv, bv, nullptr, 2, 0);

    dim3 gsc(SEQ / 128, SEQ / 128, BATCH * NH);   // 16 x 16 x 32
    scores_kernel<<<gsc, blk>>>(out);

    softmax_kernel<<<BATCH * NH * SEQ, blk>>>(out);

    dim3 gav(1, SEQ / 128, BATCH * NH);    // 1 x 16 x 32
    av_kernel<<<gav, blk>>>(out);

    proj_kernel<<<gproj, blk>>>(nullptr, Wo, bo, out, 3, 1);
}

// round 2
// speedup vs baseline: 1.0520x; 1.0520x over previous
#include <cuda_runtime.h>
#include <math.h>

#define BATCH 2
#define SEQ   2048
#define NH    16
#define DK    64
#define DM    1024
#define MTOT  (BATCH*SEQ)          // 4096

// d_out layout: [out 4194304][std_w 100663296][spec_w 33554432]
#define STD_OFF  4194304ull
#define SPEC_OFF 104857600ull

// scratch (no allocations allowed)
__device__ float g_q[(size_t)BATCH*NH*SEQ*DK];
__device__ float g_k[(size_t)BATCH*NH*SEQ*DK];
__device__ float g_v[(size_t)BATCH*NH*SEQ*DK];
__device__ float g_attn[(size_t)BATCH*SEQ*DM];

__device__ __forceinline__ float* head_w_ptr(float* dout, int bh) {
    int b = bh >> 4, h = bh & 15;
    size_t off;
    if (h < 12) off = STD_OFF  + ((size_t)(b * 12 + h))      * SEQ * SEQ;
    else        off = SPEC_OFF + ((size_t)(b * 4 + (h - 12))) * SEQ * SEQ;
    return dout + off;
}

// ---------------------------------------------------------------------------
// Generic projection GEMM: C = A[M,K=1024] @ W[1024, N=1024] + bias
// which: 0->g_q, 1->g_k, 2->g_v (scatter to [B,H,S,Dk]), 3->Cout row-major
// a_is_attn: read A from g_attn instead of param pointer.
// Tile 128x128x8, 256 threads, 8x8 per thread (4+4 split).
// ---------------------------------------------------------------------------
__global__ __launch_bounds__(256) void proj_kernel(
    const float* __restrict__ A, const float* __restrict__ W,
    const float* __restrict__ bias, float* __restrict__ Cout,
    int which, int a_is_attn)
{
    const int K = DM, N = DM;
    __shared__ float As[8][128];
    __shared__ float Bs[8][128];

    const float* Abase = a_is_attn ? (const float*)g_attn : A;

    int tid = threadIdx.x;
    int bm = blockIdx.y * 128, bn = blockIdx.x * 128;
    int a_row = tid >> 1, a_col = (tid & 1) * 4;
    int b_row = tid >> 5, b_col = (tid & 31) * 4;
    int ty = tid >> 4, tx = tid & 15;

    float acc[8][8];
#pragma unroll
    for (int i = 0; i < 8; i++)
#pragma unroll
        for (int j = 0; j < 8; j++) acc[i][j] = 0.f;

    const float* Ap = Abase + (size_t)(bm + a_row) * K + a_col;
    const float* Wp = W + (size_t)b_row * N + bn + b_col;

    for (int k0 = 0; k0 < K; k0 += 8) {
        float4 av = *(const float4*)(Ap + k0);
        float4 bv = *(const float4*)(Wp + (size_t)k0 * N);
        As[a_col + 0][a_row] = av.x;
        As[a_col + 1][a_row] = av.y;
        As[a_col + 2][a_row] = av.z;
        As[a_col + 3][a_row] = av.w;
        *(float4*)&Bs[b_row][b_col] = bv;
        __syncthreads();
#pragma unroll
        for (int kk = 0; kk < 8; kk++) {
            float a[8], b[8];
            *(float4*)(a)     = *(const float4*)&As[kk][ty * 4];
            *(float4*)(a + 4) = *(const float4*)&As[kk][64 + ty * 4];
            *(float4*)(b)     = *(const float4*)&Bs[kk][tx * 4];
            *(float4*)(b + 4) = *(const float4*)&Bs[kk][64 + tx * 4];
#pragma unroll
            for (int i = 0; i < 8; i++)
#pragma unroll
                for (int j = 0; j < 8; j++)
                    acc[i][j] = fmaf(a[i], b[j], acc[i][j]);
        }
        __syncthreads();
    }

    float* qkv = (which == 0) ? g_q : (which == 1) ? g_k : g_v;
#pragma unroll
    for (int i = 0; i < 8; i++) {
        int m = bm + ((i < 4) ? ty * 4 + i : 64 + ty * 4 + (i - 4));
#pragma unroll
        for (int j = 0; j < 8; j++) {
            int n = bn + ((j < 4) ? tx * 4 + j : 64 + tx * 4 + (j - 4));
            float v = acc[i][j] + bias[n];
            if (which < 3) {
                int b_ = m >> 11, s = m & 2047, h = n >> 6, d = n & 63;
                qkv[((((size_t)b_ * NH) + h) * SEQ + s) * DK + d] = v;
            } else {
                Cout[(size_t)m * N + n] = v;
            }
        }
    }
}

// ---------------------------------------------------------------------------
// Scores: per head, S = q @ k^T * (1/8), written straight into d_out weights.
// Tile 128x128, K=64 (8 iters of BK=8). grid (16,16,32)
// ---------------------------------------------------------------------------
__global__ __launch_bounds__(256) void scores_kernel(float* __restrict__ dout)
{
    int bh = blockIdx.z;
    const float* q = g_q + (size_t)bh * SEQ * DK;
    const float* k = g_k + (size_t)bh * SEQ * DK;
    float* outp = head_w_ptr(dout, bh);

    __shared__ float As[8][128];
    __shared__ float Bs[8][128];

    int tid = threadIdx.x;
    int bm = blockIdx.y * 128, bn = blockIdx.x * 128;
    int r = tid >> 1, c = (tid & 1) * 4;
    int ty = tid >> 4, tx = tid & 15;

    float acc[8][8];
#pragma unroll
    for (int i = 0; i < 8; i++)
#pragma unroll
        for (int j = 0; j < 8; j++) acc[i][j] = 0.f;

    const float* qp = q + (size_t)(bm + r) * DK + c;
    const float* kp = k + (size_t)(bn + r) * DK + c;

    for (int k0 = 0; k0 < DK; k0 += 8) {
        float4 av = *(const float4*)(qp + k0);
        float4 bv = *(const float4*)(kp + k0);
        As[c + 0][r] = av.x; As[c + 1][r] = av.y;
        As[c + 2][r] = av.z; As[c + 3][r] = av.w;
        Bs[c + 0][r] = bv.x; Bs[c + 1][r] = bv.y;
        Bs[c + 2][r] = bv.z; Bs[c + 3][r] = bv.w;
        __syncthreads();
#pragma unroll
        for (int kk = 0; kk < 8; kk++) {
            float a[8], b[8];
            *(float4*)(a)     = *(const float4*)&As[kk][ty * 4];
            *(float4*)(a + 4) = *(const float4*)&As[kk][64 + ty * 4];
            *(float4*)(b)     = *(const float4*)&Bs[kk][tx * 4];
            *(float4*)(b + 4) = *(const float4*)&Bs[kk][64 + tx * 4];
#pragma unroll
            for (int i = 0; i < 8; i++)
#pragma unroll
                for (int j = 0; j < 8; j++)
                    acc[i][j] = fmaf(a[i], b[j], acc[i][j]);
        }
        __syncthreads();
    }

#pragma unroll
    for (int i = 0; i < 8; i++) {
        int m = bm + ((i < 4) ? ty * 4 + i : 64 + ty * 4 + (i - 4));
#pragma unroll
        for (int j = 0; j < 8; j++) {
            int n = bn + ((j < 4) ? tx * 4 + j : 64 + tx * 4 + (j - 4));
            outp[(size_t)m * SEQ + n] = acc[i][j] * 0.125f;
        }
    }
}

// ---------------------------------------------------------------------------
// In-place row softmax over the weights region. 1 block = 1 row of 2048.
// grid = B*H*S = 65536 blocks, 256 threads (8 values / thread).
// ---------------------------------------------------------------------------
__global__ __launch_bounds__(256) void softmax_kernel(float* __restrict__ dout)
{
    int row = blockIdx.x;
    int bh = row >> 11, r = row & 2047;
    float* p = head_w_ptr(dout, bh) + (size_t)r * SEQ;

    int tid = threadIdx.x;
    float4 v0 = *(const float4*)(p + tid * 8);
    float4 v1 = *(const float4*)(p + tid * 8 + 4);
    float vals[8] = {v0.x, v0.y, v0.z, v0.w, v1.x, v1.y, v1.z, v1.w};

    __shared__ float red[8];

    float mx = vals[0];
#pragma unroll
    for (int i = 1; i < 8; i++) mx = fmaxf(mx, vals[i]);
#pragma unroll
    for (int off = 16; off; off >>= 1)
        mx = fmaxf(mx, __shfl_xor_sync(0xffffffffu, mx, off));
    if ((tid & 31) == 0) red[tid >> 5] = mx;
    __syncthreads();
    mx = red[0];
#pragma unroll
    for (int w = 1; w < 8; w++) mx = fmaxf(mx, red[w]);
    __syncthreads();

    float s = 0.f;
#pragma unroll
    for (int i = 0; i < 8; i++) { vals[i] = __expf(vals[i] - mx); s += vals[i]; }
#pragma unroll
    for (int off = 16; off; off >>= 1)
        s += __shfl_xor_sync(0xffffffffu, s, off);
    if ((tid & 31) == 0) red[tid >> 5] = s;
    __syncthreads();
    s = red[0];
#pragma unroll
    for (int w = 1; w < 8; w++) s += red[w];

    float inv = 1.0f / s;
    float4 o0 = make_float4(vals[0] * inv, vals[1] * inv, vals[2] * inv, vals[3] * inv);
    float4 o1 = make_float4(vals[4] * inv, vals[5] * inv, vals[6] * inv, vals[7] * inv);
    *(float4*)(p + tid * 8) = o0;
    *(float4*)(p + tid * 8 + 4) = o1;
}

// ---------------------------------------------------------------------------
// AV: per head, O[S,64] = W[S,S] @ V[S,64]; write to g_attn [B,S,H,Dk].
// Tile 128x64x16, 256 threads, 8x4 per thread. grid (1,16,32)
// ---------------------------------------------------------------------------
__global__ __launch_bounds__(256) void av_kernel(float* __restrict__ dout)
{
    int bh = blockIdx.z;
    int b = bh >> 4, h = bh & 15;
    const float* Wm = head_w_ptr(dout, bh);
    const float* V = g_v + (size_t)bh * SEQ * DK;

    __shared__ float As[16][128];
    __shared__ float Bs[16][64];

    int tid = threadIdx.x;
    int bm = blockIdx.y * 128;
    int a_row = tid & 127, a_c0 = (tid >> 7) * 8;
    int b_row = tid >> 4, b_col = (tid & 15) * 4;
    int ty = tid >> 4, tx = tid & 15;

    float acc[8][4];
#pragma unroll
    for (int i = 0; i < 8; i++)
#pragma unroll
        for (int j = 0; j < 4; j++) acc[i][j] = 0.f;

    const float* Wp = Wm + (size_t)(bm + a_row) * SEQ + a_c0;
    const float* Vp = V + (size_t)b_row * DK + b_col;

    for (int k0 = 0; k0 < SEQ; k0 += 16) {
        float4 a0 = *(const float4*)(Wp + k0);
        float4 a1 = *(const float4*)(Wp + k0 + 4);
        float4 bv = *(const float4*)(Vp + (size_t)k0 * DK);
        As[a_c0 + 0][a_row] = a0.x; As[a_c0 + 1][a_row] = a0.y;
        As[a_c0 + 2][a_row] = a0.z; As[a_c0 + 3][a_row] = a0.w;
        As[a_c0 + 4][a_row] = a1.x; As[a_c0 + 5][a_row] = a1.y;
        As[a_c0 + 6][a_row] = a1.z; As[a_c0 + 7][a_row] = a1.w;
        *(float4*)&Bs[b_row][b_col] = bv;
        __syncthreads();
#pragma unroll
        for (int kk = 0; kk < 16; kk++) {
            float a[8], bb[4];
            *(float4*)(a)     = *(const float4*)&As[kk][ty * 4];
            *(float4*)(a + 4) = *(const float4*)&As[kk][64 + ty * 4];
            *(float4*)(bb)    = *(const float4*)&Bs[kk][tx * 4];
#pragma unroll
            for (int i = 0; i < 8; i++)
#pragma unroll
                for (int j = 0; j < 4; j++)
                    acc[i][j] = fmaf(a[i], bb[j], acc[i][j]);
        }
        __syncthreads();
    }

#pragma unroll
    for (int i = 0; i < 8; i++) {
        int s = bm + ((i < 4) ? ty * 4 + i : 64 + ty * 4 + (i - 4));
#pragma unroll
        for (int j = 0; j < 4; j++) {
            int d = tx * 4 + j;
            g_attn[(((size_t)b * SEQ + s) * NH + h) * DK + d] = acc[i][j];
        }
    }
}

// ---------------------------------------------------------------------------
extern "C" void kernel_launch(void* const* d_in, const int* in_sizes, int n_in,
                              void* d_out, int out_size)
{
    const float* x  = (const float*)d_in[0];
    // d_in[1] = input_ids (unused by reference math)
    const float* Wq = (const float*)d_in[2];
    const float* bq = (const float*)d_in[3];
    const float* Wk = (const float*)d_in[4];
    const float* bk = (const float*)d_in[5];
    const float* Wv = (const float*)d_in[6];
    const float* bv = (const float*)d_in[7];
    const float* Wo = (const float*)d_in[8];
    const float* bo = (const float*)d_in[9];
    float* out = (float*)d_out;

    dim3 blk(256);
    dim3 gproj(DM / 128, MTOT / 128);      // 8 x 32

    proj_kernel<<<gproj, blk>>>(x, Wq, bq, nullptr, 0, 0);
    proj_kernel<<<gproj, blk>>>(x, Wk, bk, nullptr, 1, 0);
    proj_kernel<<<gproj, blk>>>(x, Wv, bv, nullptr, 2, 0);

    dim3 gsc(SEQ / 128, SEQ / 128, BATCH * NH);   // 16 x 16 x 32
    scores_kernel<<<gsc, blk>>>(out);

    softmax_kernel<<<BATCH * NH * SEQ, blk>>>(out);

    dim3 gav(1, SEQ / 128, BATCH * NH);    // 1 x 16 x 32
    av_kernel<<<gav, blk>>>(out);

    proj_kernel<<<gproj, blk>>>(nullptr, Wo, bo, out, 3, 1);
}

// round 4
// speedup vs baseline: 3.0097x; 2.8610x over previous
#include <cuda_runtime.h>
#include <cstdint>
#include <math.h>

#define BATCH 2
#define SEQ   2048
#define NH    16
#define DK    64
#define DM    1024
#define MTOT  4096

#define STD_OFF  4194304ull
#define SPEC_OFF 104857600ull

// ------------- scratch (no allocations allowed) -------------
__device__ float g_xr[(size_t)MTOT*DM];             // tf32(x)
__device__ float g_wt[(size_t)4*DM*DM];             // W^T tf32 (q,k,v,o)
__device__ float g_q [(size_t)BATCH*NH*SEQ*DK];     // [B,H,S,Dk] tf32
__device__ float g_k [(size_t)BATCH*NH*SEQ*DK];
__device__ float g_vt[(size_t)BATCH*NH*DK*SEQ];     // [B,H,Dk,S] tf32
__device__ float g_attn[(size_t)MTOT*DM];           // tf32
__device__ float g_psum[(size_t)16*BATCH*NH*SEQ];   // partial row sums per n-tile

// ------------- helpers -------------
__device__ __forceinline__ float to_tf32(float x) {
    float r; asm("cvt.rna.tf32.f32 %0, %1;" : "=f"(r) : "f"(x)); return r;
}
__device__ __forceinline__ uint32_t smem_u32(const void* p) {
    uint32_t a;
    asm("{ .reg .u64 t; cvta.to.shared.u64 t, %1; cvt.u32.u64 %0, t; }" : "=r"(a) : "l"(p));
    return a;
}
#define CPA(d, s) asm volatile("cp.async.cg.shared.global [%0], [%1], 16;" :: "r"(d), "l"(s))
#define CPC()  asm volatile("cp.async.commit_group;")
#define CPW0() asm volatile("cp.async.wait_group 0;" ::: "memory")
#define CPW1() asm volatile("cp.async.wait_group 1;" ::: "memory")

#define MMA8(d, a, b) \
    asm volatile("mma.sync.aligned.m16n8k8.row.col.f32.tf32.tf32.f32 " \
        "{%0,%1,%2,%3}, {%4,%5,%6,%7}, {%8,%9}, {%0,%1,%2,%3};" \
        : "+f"((d)[0]), "+f"((d)[1]), "+f"((d)[2]), "+f"((d)[3]) \
        : "r"((a)[0]), "r"((a)[1]), "r"((a)[2]), "r"((a)[3]), "r"((b)[0]), "r"((b)[1]))

// SW128-style swizzle for tiles with 32-float (128B) rows.
__device__ __forceinline__ int swi(int row, int k) {          // float index
    return row * 32 + (((k >> 2) ^ (row & 7)) << 2) + (k & 3);
}
__device__ __forceinline__ uint32_t swc(uint32_t base, int row, int c) { // byte addr, 16B chunk c
    return base + row * 128 + ((c ^ (row & 7)) << 4);
}

__device__ __forceinline__ float* head_w_ptr(float* dout, int bh) {
    int b = bh >> 4, h = bh & 15;
    size_t off;
    if (h < 12) off = STD_OFF  + ((size_t)(b * 12 + h)) * SEQ * SEQ;
    else        off = SPEC_OFF + ((size_t)(b * 4 + (h - 12))) * SEQ * SEQ;
    return dout + off;
}

// ---------------------------------------------------------------------------
// round x to tf32
// ---------------------------------------------------------------------------
__global__ __launch_bounds__(256) void round_x(const float4* __restrict__ x)
{
    int i = blockIdx.x * 256 + threadIdx.x;   // n4 = 1048576, grid 4096
    float4 v = x[i];
    v.x = to_tf32(v.x); v.y = to_tf32(v.y); v.z = to_tf32(v.z); v.w = to_tf32(v.w);
    ((float4*)g_xr)[i] = v;
}

// ---------------------------------------------------------------------------
// W^T + tf32 rounding: g_wt[z][n][k] = tf32(W[k][n])
// ---------------------------------------------------------------------------
__global__ __launch_bounds__(256) void transpose_w(
    const float* __restrict__ w0, const float* __restrict__ w1,
    const float* __restrict__ w2, const float* __restrict__ w3)
{
    __shared__ float t[32][33];
    int z = blockIdx.z;
    const float* src = (z == 0) ? w0 : (z == 1) ? w1 : (z == 2) ? w2 : w3;
    float* dst = g_wt + (size_t)z * DM * DM;
    int x = blockIdx.x * 32 + threadIdx.x;
    int y0 = blockIdx.y * 32;
    for (int i = threadIdx.y; i < 32; i += 8)
        t[i][threadIdx.x] = src[(size_t)(y0 + i) * DM + x];
    __syncthreads();
    int kx = y0 + threadIdx.x;
    int n0 = blockIdx.x * 32;
    for (int i = threadIdx.y; i < 32; i += 8)
        dst[(size_t)(n0 + i) * DM + kx] = to_tf32(t[threadIdx.x][i]);
}

// ---------------------------------------------------------------------------
// Projection GEMM: C[4096,1024] = A @ W^T + bias. Block 128x128, K=1024.
// 8 warps: wm = w>>2 (2 x 64 rows), wn = w&3 (4 x 32 cols); warp tile 64x32.
// which: 0->g_q 1->g_k 2->g_vt(transposed) 3->d_out (A = g_attn)
// dyn smem (floats): A[2][4096] @0, B[2][4096] @8192  (64KB)
// ---------------------------------------------------------------------------
__global__ __launch_bounds__(256, 2) void proj_mm(
    const float* __restrict__ bias, float* __restrict__ Cout, int which)
{
    extern __shared__ float sm[];
    uint32_t smb = smem_u32(sm);
    const int tid = threadIdx.x;
    const int w = tid >> 5, lane = tid & 31, g = lane >> 2, tg = lane & 3;
    const int wm = w >> 2, wn = w & 3;
    const int bn = blockIdx.x * 128, bm = blockIdx.y * 128;
    const float* Ap = (which == 3) ? (const float*)g_attn : (const float*)g_xr;
    const float* Wt = g_wt + (size_t)which * DM * DM;

    float acc[4][4][4];
#pragma unroll
    for (int i = 0; i < 4; i++)
#pragma unroll
        for (int j = 0; j < 4; j++)
#pragma unroll
            for (int e = 0; e < 4; e++) acc[i][j][e] = 0.f;

    const int r8 = tid >> 3, c8 = tid & 7;
    auto load = [&](int c, int buf) {
        const float* as = Ap + (size_t)bm * DM + c * 32;
        const float* bs = Wt + (size_t)bn * DM + c * 32;
        uint32_t ab = smb + buf * 16384, bb = smb + 32768 + buf * 16384;
#pragma unroll
        for (int j = 0; j < 4; j++) {
            int r = r8 + 32 * j;
            CPA(swc(ab, r, c8), as + (size_t)r * DM + c8 * 4);
            CPA(swc(bb, r, c8), bs + (size_t)r * DM + c8 * 4);
        }
        CPC();
    };
    auto compute = [&](int buf) {
        const float* A = sm + buf * 4096;
        const float* B = sm + 8192 + buf * 4096;
#pragma unroll
        for (int ks = 0; ks < 4; ks++) {
            int k0 = ks * 8;
            uint32_t a[4][4], b[4][2];
#pragma unroll
            for (int mf = 0; mf < 4; mf++) {
                int row = wm * 64 + mf * 16 + g;
                a[mf][0] = __float_as_uint(A[swi(row,     k0 + tg)]);
                a[mf][1] = __float_as_uint(A[swi(row + 8, k0 + tg)]);
                a[mf][2] = __float_as_uint(A[swi(row,     k0 + 4 + tg)]);
                a[mf][3] = __float_as_uint(A[swi(row + 8, k0 + 4 + tg)]);
            }
#pragma unroll
            for (int nf = 0; nf < 4; nf++) {
                int rn = wn * 32 + nf * 8 + g;
                b[nf][0] = __float_as_uint(B[swi(rn, k0 + tg)]);
                b[nf][1] = __float_as_uint(B[swi(rn, k0 + 4 + tg)]);
            }
#pragma unroll
            for (int mf = 0; mf < 4; mf++)
#pragma unroll
                for (int nf = 0; nf < 4; nf++)
                    MMA8(acc[mf][nf], a[mf], b[nf]);
        }
    };

    load(0, 0); load(1, 1);
    const int NC = DM / 32;
    for (int c = 0; c < NC; c++) {
        if (c < NC - 1) { CPW1(); } else { CPW0(); }
        __syncthreads();
        compute(c & 1);
        __syncthreads();
        if (c + 2 < NC) load(c + 2, c & 1);
    }

#pragma unroll
    for (int mf = 0; mf < 4; mf++)
#pragma unroll
    for (int half = 0; half < 2; half++) {
        int m = bm + wm * 64 + mf * 16 + g + half * 8;
#pragma unroll
        for (int nf = 0; nf < 4; nf++) {
            int n = bn + wn * 32 + nf * 8 + 2 * tg;
            float v0 = acc[mf][nf][2 * half]     + bias[n];
            float v1 = acc[mf][nf][2 * half + 1] + bias[n + 1];
            if (which == 3) {
                *(float2*)(Cout + (size_t)m * DM + n) = make_float2(v0, v1);
            } else {
                int b_ = m >> 11, s = m & 2047, h = n >> 6, d = n & 63;
                if (which == 2) {
                    g_vt[(((size_t)(b_ * NH + h)) * DK + d)     * SEQ + s] = to_tf32(v0);
                    g_vt[(((size_t)(b_ * NH + h)) * DK + d + 1) * SEQ + s] = to_tf32(v1);
                } else {
                    float* qk = which ? g_k : g_q;
                    *(float2*)(qk + (((size_t)(b_ * NH + h)) * SEQ + s) * DK + d) =
                        make_float2(to_tf32(v0), to_tf32(v1));
                }
            }
        }
    }
}

// ---------------------------------------------------------------------------
// scores+exp: block = (ntile 128 keys, mtile 128 q-rows, head). K = 64.
// Writes UNNORMALIZED tf32(exp(score)) to d_out; partial row sums to g_psum.
// dyn smem (floats): Q [2 panels][4096] @0, K [2 panels][4096] @8192  (64KB)
// ---------------------------------------------------------------------------
__global__ __launch_bounds__(256, 2) void scores_exp(float* __restrict__ dout)
{
    extern __shared__ float sm[];
    __shared__ float s_part[4][128];
    uint32_t smb = smem_u32(sm);
    const int tid = threadIdx.x;
    const int w = tid >> 5, lane = tid & 31, g = lane >> 2, tg = lane & 3;
    const int wm = w >> 2, wn = w & 3;
    const int nt = blockIdx.x, mt = blockIdx.y, bh = blockIdx.z;
    const int n0 = nt * 128, m0 = mt * 128;
    const float* qsrc = g_q + (size_t)bh * SEQ * DK;
    const float* ksrc = g_k + (size_t)bh * SEQ * DK;
    float* wp = head_w_ptr(dout, bh);

#pragma unroll
    for (int j = 0; j < 8; j++) {
        int idx = tid + 256 * j;
        int r = idx >> 4, ch = idx & 15;
        int p = ch >> 3, cc = ch & 7;
        CPA(swc(smb + p * 16384,         r, cc), qsrc + (size_t)(m0 + r) * DK + ch * 4);
        CPA(swc(smb + 32768 + p * 16384, r, cc), ksrc + (size_t)(n0 + r) * DK + ch * 4);
    }
    CPC(); CPW0();
    __syncthreads();

    float acc[4][4][4];
#pragma unroll
    for (int i = 0; i < 4; i++)
#pragma unroll
        for (int j = 0; j < 4; j++)
#pragma unroll
            for (int e = 0; e < 4; e++) acc[i][j][e] = 0.f;

#pragma unroll
    for (int ks = 0; ks < 8; ks++) {
        const float* A = sm + (ks >> 2) * 4096;
        const float* B = sm + 8192 + (ks >> 2) * 4096;
        int k0 = (ks & 3) * 8;
        uint32_t a[4][4], b[4][2];
#pragma unroll
        for (int mf = 0; mf < 4; mf++) {
            int row = wm * 64 + mf * 16 + g;
            a[mf][0] = __float_as_uint(A[swi(row,     k0 + tg)]);
            a[mf][1] = __float_as_uint(A[swi(row + 8, k0 + tg)]);
            a[mf][2] = __float_as_uint(A[swi(row,     k0 + 4 + tg)]);
            a[mf][3] = __float_as_uint(A[swi(row + 8, k0 + 4 + tg)]);
        }
#pragma unroll
        for (int nf = 0; nf < 4; nf++) {
            int rn = wn * 32 + nf * 8 + g;
            b[nf][0] = __float_as_uint(B[swi(rn, k0 + tg)]);
            b[nf][1] = __float_as_uint(B[swi(rn, k0 + 4 + tg)]);
        }
#pragma unroll
        for (int mf = 0; mf < 4; mf++)
#pragma unroll
            for (int nf = 0; nf < 4; nf++)
                MMA8(acc[mf][nf], a[mf], b[nf]);
    }

    float rs[4][2];
#pragma unroll
    for (int mf = 0; mf < 4; mf++) {
        rs[mf][0] = 0.f; rs[mf][1] = 0.f;
#pragma unroll
        for (int half = 0; half < 2; half++) {
            int rl = wm * 64 + mf * 16 + g + half * 8;
#pragma unroll
            for (int nf = 0; nf < 4; nf++) {
                int n = wn * 32 + nf * 8 + 2 * tg;
                float e0 = to_tf32(__expf(acc[mf][nf][2 * half]     * 0.125f));
                float e1 = to_tf32(__expf(acc[mf][nf][2 * half + 1] * 0.125f));
                rs[mf][half] += e0 + e1;
                *(float2*)(wp + (size_t)(m0 + rl) * SEQ + n0 + n) = make_float2(e0, e1);
            }
        }
    }
#pragma unroll
    for (int mf = 0; mf < 4; mf++)
#pragma unroll
    for (int half = 0; half < 2; half++) {
        float v = rs[mf][half];
        v += __shfl_xor_sync(0xffffffffu, v, 1);
        v += __shfl_xor_sync(0xffffffffu, v, 2);
        if (tg == 0) s_part[wn][wm * 64 + mf * 16 + g + half * 8] = v;
    }
    __syncthreads();
    if (tid < 128) {
        float s = s_part[0][tid] + s_part[1][tid] + s_part[2][tid] + s_part[3][tid];
        g_psum[(size_t)nt * 65536 + (size_t)bh * SEQ + m0 + tid] = s;
    }
}

// ---------------------------------------------------------------------------
// avnorm: block = (mtile 128 rows, head). O[128,64] = Wexp @ V^T, K=2048.
// Streams weight tiles: normalized write-back to d_out + MMA. Output *inv
// -> g_attn (tf32). 8 warps: wm = w>>2 (2x64 m), wn = w&3 (4x16 n).
// dyn smem (floats): A[2][4096] @0, B[2][2048] @8192  (48KB)
// ---------------------------------------------------------------------------
__global__ __launch_bounds__(256, 2) void avnorm(float* __restrict__ dout)
{
    extern __shared__ float sm[];
    __shared__ float s_inv[128];
    uint32_t smb = smem_u32(sm);
    const int tid = threadIdx.x;
    const int w = tid >> 5, lane = tid & 31, g = lane >> 2, tg = lane & 3;
    const int wm = w >> 2, wn = w & 3;
    const int mt = blockIdx.x, bh = blockIdx.y;
    const int m0 = mt * 128;
    const int b_ = bh >> 4, h = bh & 15;
    float* wp = head_w_ptr(dout, bh);
    const float* vt = g_vt + (size_t)bh * DK * SEQ;

    if (tid < 128) {
        float s = 0.f;
#pragma unroll
        for (int t = 0; t < 16; t++)
            s += g_psum[(size_t)t * 65536 + (size_t)bh * SEQ + m0 + tid];
        s_inv[tid] = 1.0f / s;
    }
    __syncthreads();

    float acc[4][2][4];
#pragma unroll
    for (int i = 0; i < 4; i++)
#pragma unroll
        for (int j = 0; j < 2; j++)
#pragma unroll
            for (int e = 0; e < 4; e++) acc[i][j][e] = 0.f;

    const int r8 = tid >> 3, c8 = tid & 7;
    auto load = [&](int c, int buf) {
        const float* as = wp + (size_t)m0 * SEQ + c * 32;
        uint32_t ab = smb + buf * 16384;
#pragma unroll
        for (int j = 0; j < 4; j++) {
            int r = r8 + 32 * j;
            CPA(swc(ab, r, c8), as + (size_t)r * SEQ + c8 * 4);
        }
        const float* bs = vt + c * 32;
        uint32_t bb = smb + 32768 + buf * 8192;
#pragma unroll
        for (int j = 0; j < 2; j++) {
            int r = r8 + 32 * j;
            CPA(swc(bb, r, c8), bs + (size_t)r * SEQ + c8 * 4);
        }
        CPC();
    };
    auto wback = [&](int c, int buf) {
        const float* A = sm + buf * 4096;
        float* dst = wp + (size_t)m0 * SEQ + c * 32;
#pragma unroll
        for (int j = 0; j < 4; j++) {
            int r = r8 + 32 * j;
            const float4 v = *(const float4*)(A + r * 32 + ((c8 ^ (r & 7)) << 2));
            float inv = s_inv[r];
            *(float4*)(dst + (size_t)r * SEQ + c8 * 4) =
                make_float4(v.x * inv, v.y * inv, v.z * inv, v.w * inv);
        }
    };
    auto compute = [&](int buf) {
        const float* A = sm + buf * 4096;
        const float* B = sm + 8192 + buf * 2048;
#pragma unroll
        for (int ks = 0; ks < 4; ks++) {
            int k0 = ks * 8;
            uint32_t a[4][4], b[2][2];
#pragma unroll
            for (int mf = 0; mf < 4; mf++) {
                int row = wm * 64 + mf * 16 + g;
                a[mf][0] = __float_as_uint(A[swi(row,     k0 + tg)]);
                a[mf][1] = __float_as_uint(A[swi(row + 8, k0 + tg)]);
                a[mf][2] = __float_as_uint(A[swi(row,     k0 + 4 + tg)]);
                a[mf][3] = __float_as_uint(A[swi(row + 8, k0 + 4 + tg)]);
            }
#pragma unroll
            for (int nf = 0; nf < 2; nf++) {
                int rn = wn * 16 + nf * 8 + g;
                b[nf][0] = __float_as_uint(B[swi(rn, k0 + tg)]);
                b[nf][1] = __float_as_uint(B[swi(rn, k0 + 4 + tg)]);
            }
#pragma unroll
            for (int mf = 0; mf < 4; mf++)
#pragma unroll
                for (int nf = 0; nf < 2; nf++)
                    MMA8(acc[mf][nf], a[mf], b[nf]);
        }
    };

    load(0, 0); load(1, 1);
    const int NC = SEQ / 32;   // 64
    for (int c = 0; c < NC; c++) {
        if (c < NC - 1) { CPW1(); } else { CPW0(); }
        __syncthreads();
        wback(c, c & 1);
        compute(c & 1);
        __syncthreads();
        if (c + 2 < NC) load(c + 2, c & 1);
    }

#pragma unroll
    for (int mf = 0; mf < 4; mf++)
#pragma unroll
    for (int half = 0; half < 2; half++) {
        int rl = wm * 64 + mf * 16 + g + half * 8;
        int s = m0 + rl;
        float inv = s_inv[rl];
#pragma unroll
        for (int nf = 0; nf < 2; nf++) {
            int d = wn * 16 + nf * 8 + 2 * tg;
            float v0 = to_tf32(acc[mf][nf][2 * half]     * inv);
            float v1 = to_tf32(acc[mf][nf][2 * half + 1] * inv);
            *(float2*)(g_attn + ((size_t)b_ * SEQ + s) * DM + h * DK + d) =
                make_float2(v0, v1);
        }
    }
}

// ---------------------------------------------------------------------------
extern "C" void kernel_launch(void* const* d_in, const int* in_sizes, int n_in,
                              void* d_out, int out_size)
{
    const float* x  = (const float*)d_in[0];
    const float* Wq = (const float*)d_in[2];
    const float* bq = (const float*)d_in[3];
    const float* Wk = (const float*)d_in[4];
    const float* bk = (const float*)d_in[5];
    const float* Wv = (const float*)d_in[6];
    const float* bv = (const float*)d_in[7];
    const float* Wo = (const float*)d_in[8];
    const float* bo = (const float*)d_in[9];
    float* out = (float*)d_out;

    cudaFuncSetAttribute(proj_mm,    cudaFuncAttributeMaxDynamicSharedMemorySize, 65536);
    cudaFuncSetAttribute(scores_exp, cudaFuncAttributeMaxDynamicSharedMemorySize, 65536);
    cudaFuncSetAttribute(avnorm,     cudaFuncAttributeMaxDynamicSharedMemorySize, 49152);

    round_x<<<4096, 256>>>((const float4*)x);
    transpose_w<<<dim3(32, 32, 4), dim3(32, 8)>>>(Wq, Wk, Wv, Wo);

    dim3 gproj(DM / 128, MTOT / 128);                 // 8 x 32
    proj_mm<<<gproj, 256, 65536>>>(bq, nullptr, 0);
    proj_mm<<<gproj, 256, 65536>>>(bk, nullptr, 1);
    proj_mm<<<gproj, 256, 65536>>>(bv, nullptr, 2);

    scores_exp<<<dim3(16, 16, 32), 256, 65536>>>(out);
    avnorm<<<dim3(16, 32), 256, 49152>>>(out);

    proj_mm<<<gproj, 256, 65536>>>(bo, out, 3);
}